// round 7
// baseline (speedup 1.0000x reference)
#include <cuda_runtime.h>
#include <cuda_bf16.h>

#define NN   1024
#define BB   128
#define KTOT 1152            // 1024 real + 1 aug col + padding (multiple of 128)
#define BM   64
#define BK   128
#define GX   16              // m-tiles
#define GY   9               // k-chunks (9*128 = 1152)
#define NBLK (GX*GY)         // 144
#define SW   136             // smem bf16 row stride (conflict-free)

// ---- device scratch (static: no allocation) ----
__device__ __nv_bfloat16 g_Whi[NN * KTOT];
__device__ __nv_bfloat16 g_Wlo[NN * KTOT];
__device__ __nv_bfloat16 g_Vhi[BB * KTOT];
__device__ __nv_bfloat16 g_Vlo[BB * KTOT];
__device__ float g_rs[NN];
__device__ float g_cs[NN];
__device__ float g_cpart[32];
__device__ float g_qpart[BB][NBLK];
__device__ unsigned int g_done = 0;

// ======================= prep 1: mask + hi/lo split W, row sums ==============
__global__ __launch_bounds__(256)
void rowprep(const float* __restrict__ W)
{
    const int i    = blockIdx.x * 8 + (threadIdx.x >> 5);
    const int lane = threadIdx.x & 31;

    float acc = 0.0f;
    #pragma unroll 4
    for (int c = 0; c < 32; c++) {
        int j = c * 32 + lane;
        float w = W[i * NN + j];
        if (j < i) w = 0.0f;                       // triu mask (keep j >= i)
        acc += w;
        __nv_bfloat16 hi = __float2bfloat16(w);
        float lo = w - __bfloat162float(hi);
        g_Whi[i * KTOT + j] = hi;
        g_Wlo[i * KTOT + j] = __float2bfloat16(lo);
    }
    // zero the K padding (aug col j=1024 overwritten later by vaugprep)
    for (int j = 1024 + lane; j < KTOT; j += 32) {
        g_Whi[i * KTOT + j] = __float2bfloat16(0.0f);
        g_Wlo[i * KTOT + j] = __float2bfloat16(0.0f);
    }
    #pragma unroll
    for (int o = 16; o > 0; o >>= 1) acc += __shfl_xor_sync(0xffffffffu, acc, o);
    if (lane == 0) g_rs[i] = acc;
}

// ======================= prep 2: masked col sums + C partials ================
__global__ __launch_bounds__(256)
void csprep(const float* __restrict__ W)
{
    __shared__ float colp[8][32];
    const int lane = threadIdx.x & 31;
    const int w    = threadIdx.x >> 5;
    const int j    = blockIdx.x * 32 + lane;

    float acc = 0.0f;
    for (int i = w; i < NN; i += 8) {
        float v = W[i * NN + j];
        acc += (j >= i) ? v : 0.0f;
    }
    colp[w][lane] = acc;
    __syncthreads();
    if (w == 0) {
        float cs = 0.0f;
        #pragma unroll
        for (int k = 0; k < 8; k++) cs += colp[k][lane];
        g_cs[j] = cs;
        float t = cs;
        #pragma unroll
        for (int o = 16; o > 0; o >>= 1) t += __shfl_xor_sync(0xffffffffu, t, o);
        if (lane == 0) g_cpart[blockIdx.x] = t;    // sum_j cs[j] partial -> C
    }
}

// ============= prep 3: v hi/lo split (+aug col) and W aug column =============
__global__ __launch_bounds__(128)
void vaugprep(const float* __restrict__ vec)
{
    if (blockIdx.x < BB) {
        const int b = blockIdx.x;
        for (int j = threadIdx.x; j < KTOT; j += 128) {
            float v;
            if (j < 1024)       v = vec[b * NN + j];
            else if (j == 1024) v = 1.0f;          // augmented constant
            else                v = 0.0f;
            __nv_bfloat16 hi = __float2bfloat16(v);
            g_Vhi[b * KTOT + j] = hi;
            g_Vlo[b * KTOT + j] = __float2bfloat16(v - __bfloat162float(hi));
        }
    } else {
        const int i = (blockIdx.x - BB) * 128 + threadIdx.x;   // 8 blocks x 128
        float val = -0.5f * (g_rs[i] + g_cs[i]);
        __nv_bfloat16 hi = __float2bfloat16(val);
        g_Whi[i * KTOT + 1024] = hi;
        g_Wlo[i * KTOT + 1024] = __float2bfloat16(val - __bfloat162float(hi));
    }
}

// ======================= main GEMM (bf16 split-2, mma.sync) ==================
static __device__ __forceinline__
void mma16816(float* d, const unsigned* a, unsigned b0, unsigned b1)
{
    asm volatile(
        "mma.sync.aligned.m16n8k16.row.col.f32.bf16.bf16.f32 "
        "{%0,%1,%2,%3}, {%4,%5,%6,%7}, {%8,%9}, {%0,%1,%2,%3};\n"
        : "+f"(d[0]), "+f"(d[1]), "+f"(d[2]), "+f"(d[3])
        : "r"(a[0]), "r"(a[1]), "r"(a[2]), "r"(a[3]), "r"(b0), "r"(b1));
}

// dynamic smem layout (bytes)
#define OFF_WHI  0u
#define OFF_WLO  17408u
#define OFF_VHI  34816u
#define OFF_VLO  69632u
#define OFF_VIT  104448u          // float [64][129]
#define OFF_QSM  137472u          // float [4][128]
#define OFF_RANK 139520u
#define SMEM_BYTES 139552u

__global__ __launch_bounds__(128, 1)
void potts_gemm(const float* __restrict__ vec, float* __restrict__ out)
{
    extern __shared__ char smem[];
    __nv_bfloat16* Whi_s = (__nv_bfloat16*)(smem + OFF_WHI);
    __nv_bfloat16* Wlo_s = (__nv_bfloat16*)(smem + OFF_WLO);
    __nv_bfloat16* Vhi_s = (__nv_bfloat16*)(smem + OFF_VHI);
    __nv_bfloat16* Vlo_s = (__nv_bfloat16*)(smem + OFF_VLO);
    float* ViT = (float*)(smem + OFF_VIT);           // [64][129]
    float* qsm = (float*)(smem + OFF_QSM);           // [4][128]
    unsigned* s_rank = (unsigned*)(smem + OFF_RANK);

    const int tid  = threadIdx.x;
    const int lane = tid & 31;
    const int w    = tid >> 5;            // warp: m-rows w*16..w*16+15
    const int g    = lane >> 2;
    const int t    = lane & 3;

    const int i0 = blockIdx.x * BM;       // m-tile
    const int k0 = blockIdx.y * BK;       // k-chunk

    // ---- stage W tiles (64 rows x 128 k, 16B chunks) ----
    #pragma unroll 2
    for (int idx = tid; idx < 64 * 16; idx += 128) {
        int r = idx >> 4, c = idx & 15;
        *(uint4*)(Whi_s + r * SW + c * 8) =
            *(const uint4*)(g_Whi + (i0 + r) * KTOT + k0 + c * 8);
        *(uint4*)(Wlo_s + r * SW + c * 8) =
            *(const uint4*)(g_Wlo + (i0 + r) * KTOT + k0 + c * 8);
    }
    // ---- stage V tiles (128 b x 128 k) ----
    #pragma unroll 2
    for (int idx = tid; idx < 128 * 16; idx += 128) {
        int r = idx >> 4, c = idx & 15;
        *(uint4*)(Vhi_s + r * SW + c * 8) =
            *(const uint4*)(g_Vhi + r * KTOT + k0 + c * 8);
        *(uint4*)(Vlo_s + r * SW + c * 8) =
            *(const uint4*)(g_Vlo + r * KTOT + k0 + c * 8);
    }
    // ---- stage fp32 v for epilogue: ViT[r][b] = vec[b, i0+r] ----
    for (int idx = tid; idx < 64 * 128; idx += 128) {
        int r = idx & 63, b = idx >> 6;
        ViT[r * 129 + b] = vec[b * NN + i0 + r];
    }
    __syncthreads();

    float d[16][4];
    #pragma unroll
    for (int nt = 0; nt < 16; nt++)
        #pragma unroll
        for (int k = 0; k < 4; k++) d[nt][k] = 0.0f;

    const __nv_bfloat16* Ah = Whi_s + (w * 16 + g) * SW + 2 * t;
    const __nv_bfloat16* Al = Wlo_s + (w * 16 + g) * SW + 2 * t;
    const __nv_bfloat16* Bh = Vhi_s + g * SW + 2 * t;
    const __nv_bfloat16* Bl = Vlo_s + g * SW + 2 * t;

    for (int s = 0; s < 8; s++) {
        const int ko = s * 16;
        unsigned ah[4], al[4];
        ah[0] = *(const unsigned*)(Ah + ko);
        ah[1] = *(const unsigned*)(Ah + ko + 8 * SW);
        ah[2] = *(const unsigned*)(Ah + ko + 8);
        ah[3] = *(const unsigned*)(Ah + ko + 8 * SW + 8);
        al[0] = *(const unsigned*)(Al + ko);
        al[1] = *(const unsigned*)(Al + ko + 8 * SW);
        al[2] = *(const unsigned*)(Al + ko + 8);
        al[3] = *(const unsigned*)(Al + ko + 8 * SW + 8);
        #pragma unroll
        for (int nt = 0; nt < 16; nt++) {
            const __nv_bfloat16* bph = Bh + nt * 8 * SW + ko;
            const __nv_bfloat16* bpl = Bl + nt * 8 * SW + ko;
            unsigned bh0 = *(const unsigned*)(bph);
            unsigned bh1 = *(const unsigned*)(bph + 8);
            unsigned bl0 = *(const unsigned*)(bpl);
            unsigned bl1 = *(const unsigned*)(bpl + 8);
            mma16816(d[nt], ah, bh0, bh1);   // Whi * vhi
            mma16816(d[nt], ah, bl0, bl1);   // Whi * vlo
            mma16816(d[nt], al, bh0, bh1);   // Wlo * vhi
        }
    }

    // ---- epilogue: q_partial[b] = sum_i v[b,i] * T[i,b] ----
    {
        const int r = w * 16 + g;
        #pragma unroll
        for (int nt = 0; nt < 16; nt++) {
            const int b0 = nt * 8 + 2 * t;
            float sA = d[nt][0] * ViT[r * 129 + b0]
                     + d[nt][2] * ViT[(r + 8) * 129 + b0];
            float sB = d[nt][1] * ViT[r * 129 + b0 + 1]
                     + d[nt][3] * ViT[(r + 8) * 129 + b0 + 1];
            #pragma unroll
            for (int o = 4; o <= 16; o <<= 1) {
                sA += __shfl_xor_sync(0xffffffffu, sA, o);
                sB += __shfl_xor_sync(0xffffffffu, sB, o);
            }
            if (g == 0) {                       // lanes 0..3 hold totals
                qsm[w * 128 + b0]     = sA;
                qsm[w * 128 + b0 + 1] = sB;
            }
        }
    }
    __syncthreads();

    const int blin = blockIdx.y * GX + blockIdx.x;
    float qp = qsm[tid] + qsm[128 + tid] + qsm[256 + tid] + qsm[384 + tid];
    g_qpart[tid][blin] = qp;

    // ---- ticket-based fused final reduce ----
    __threadfence();
    __syncthreads();
    if (tid == 0) *s_rank = atomicAdd(&g_done, 1u);
    __syncthreads();
    if (*s_rank == NBLK - 1) {
        __threadfence();
        float s = 0.0f;
        const float4* p = (const float4*)(&g_qpart[tid][0]);
        #pragma unroll 4
        for (int k = 0; k < NBLK / 4; k++) {
            float4 v4 = p[k];
            s += v4.x + v4.y + v4.z + v4.w;
        }
        float C = 0.0f;
        #pragma unroll
        for (int k = 0; k < 32; k++) C += g_cpart[k];
        out[tid] = C + 2.0f * s;
        if (tid == 0) g_done = 0;               // reset for next replay
    }
}

extern "C" void kernel_launch(void* const* d_in, const int* in_sizes, int n_in,
                              void* d_out, int out_size)
{
    const float* vec = (const float*)d_in[0];   // vector        [128, 1024]
    const float* W   = (const float*)d_in[1];   // interactions  [1024, 1024]
    float* out = (float*)d_out;                 // [128]

    cudaFuncSetAttribute(potts_gemm,
                         cudaFuncAttributeMaxDynamicSharedMemorySize, SMEM_BYTES);

    rowprep<<<128, 256>>>(W);
    csprep<<<32, 256>>>(W);
    vaugprep<<<BB + 8, 128>>>(vec);
    potts_gemm<<<dim3(GX, GY), 128, SMEM_BYTES>>>(vec, out);
}

// round 8
// speedup vs baseline: 1.1265x; 1.1265x over previous
#include <cuda_runtime.h>
#include <cuda_bf16.h>

#define NN   1024
#define BB   128
#define BM   32
#define BK   64
#define NMT  32              // m-tiles
#define NKC  16              // k-chunks
#define NBLK 272             // active (mt,kc): kc >= mt/2
#define SW   72              // smem bf16 row stride (16B aligned, conflict-free)

// ---- device scratch (static; no allocation) ----
__device__ __nv_bfloat16 g_Whi[NN * NN];
__device__ __nv_bfloat16 g_Wlo[NN * NN];
__device__ __nv_bfloat16 g_Vhi[BB * NN];
__device__ __nv_bfloat16 g_Vlo[BB * NN];
__device__ float g_rs[NN];
__device__ float g_L[NN];          // -(rs+cs)/2
__device__ float g_cpart[32];      // partials of C = sum of masked W
__device__ float g_qpart[BB][NBLK];
__device__ unsigned int g_done = 0;

// ======================= prep 1: mask + hi/lo split W, row sums ==============
__global__ __launch_bounds__(256)
void rowprep(const float* __restrict__ W)
{
    const int i    = blockIdx.x * 8 + (threadIdx.x >> 5);
    const int lane = threadIdx.x & 31;

    float acc = 0.0f;
    #pragma unroll 4
    for (int c = 0; c < 32; c++) {
        int j = c * 32 + lane;
        float w = W[i * NN + j];
        if (j < i) w = 0.0f;                       // triu mask
        acc += w;
        __nv_bfloat16 hi = __float2bfloat16(w);
        g_Whi[i * NN + j] = hi;
        g_Wlo[i * NN + j] = __float2bfloat16(w - __bfloat162float(hi));
    }
    #pragma unroll
    for (int o = 16; o > 0; o >>= 1) acc += __shfl_xor_sync(0xffffffffu, acc, o);
    if (lane == 0) g_rs[i] = acc;
}

// ================ prep 2: masked col sums, C partials, L = -(rs+cs)/2 ========
__global__ __launch_bounds__(256)
void csprep(const float* __restrict__ W)
{
    __shared__ float colp[8][32];
    const int lane = threadIdx.x & 31;
    const int w    = threadIdx.x >> 5;
    const int j    = blockIdx.x * 32 + lane;

    float acc = 0.0f;
    for (int i = w; i < NN; i += 8) {
        float v = W[i * NN + j];
        acc += (j >= i) ? v : 0.0f;
    }
    colp[w][lane] = acc;
    __syncthreads();
    if (w == 0) {
        float cs = 0.0f;
        #pragma unroll
        for (int k = 0; k < 8; k++) cs += colp[k][lane];
        g_L[j] = -0.5f * (g_rs[j] + cs);
        float t = cs;
        #pragma unroll
        for (int o = 16; o > 0; o >>= 1) t += __shfl_xor_sync(0xffffffffu, t, o);
        if (lane == 0) g_cpart[blockIdx.x] = t;
    }
}

// ======================= prep 3: v hi/lo split ===============================
__global__ __launch_bounds__(256)
void vprep(const float* __restrict__ vec)
{
    const int b = blockIdx.x;
    for (int j = threadIdx.x; j < NN; j += 256) {
        float v = vec[b * NN + j];
        __nv_bfloat16 hi = __float2bfloat16(v);
        g_Vhi[b * NN + j] = hi;
        g_Vlo[b * NN + j] = __float2bfloat16(v - __bfloat162float(hi));
    }
}

// ======================= main GEMM ===========================================
static __device__ __forceinline__
void mma16816(float* d, const unsigned* a, unsigned b0, unsigned b1)
{
    asm volatile(
        "mma.sync.aligned.m16n8k16.row.col.f32.bf16.bf16.f32 "
        "{%0,%1,%2,%3}, {%4,%5,%6,%7}, {%8,%9}, {%0,%1,%2,%3};\n"
        : "+f"(d[0]), "+f"(d[1]), "+f"(d[2]), "+f"(d[3])
        : "r"(a[0]), "r"(a[1]), "r"(a[2]), "r"(a[3]), "r"(b0), "r"(b1));
}

static __device__ __forceinline__
void ldsm4(unsigned* r, unsigned addr)
{
    asm volatile("ldmatrix.sync.aligned.m8n8.x4.shared.b16 {%0,%1,%2,%3}, [%4];"
                 : "=r"(r[0]), "=r"(r[1]), "=r"(r[2]), "=r"(r[3]) : "r"(addr));
}

// smem layout (bytes)
#define OFF_WHI   0u
#define OFF_WLO   4608u
#define OFF_VHI   9216u
#define OFF_VLO   27648u
#define OFF_VIT   46080u     // float [32][129]
#define OFF_LS    62592u     // float [32]
#define OFF_QSM   62720u     // float [8][32]
#define OFF_RANK  63744u
#define SMEM_BYTES 63760u

__global__ __launch_bounds__(256, 2)
void potts_gemm(const float* __restrict__ vec, float* __restrict__ out)
{
    extern __shared__ char smem[];
    __nv_bfloat16* Whi_s = (__nv_bfloat16*)(smem + OFF_WHI);
    __nv_bfloat16* Wlo_s = (__nv_bfloat16*)(smem + OFF_WLO);
    __nv_bfloat16* Vhi_s = (__nv_bfloat16*)(smem + OFF_VHI);
    __nv_bfloat16* Vlo_s = (__nv_bfloat16*)(smem + OFF_VLO);
    float* ViT = (float*)(smem + OFF_VIT);            // [32][129]
    float* Ls  = (float*)(smem + OFF_LS);
    float* qsm = (float*)(smem + OFF_QSM);            // [8][32]
    unsigned* s_rank = (unsigned*)(smem + OFF_RANK);
    const unsigned sbase = (unsigned)__cvta_generic_to_shared(smem);

    const int tid  = threadIdx.x;
    const int lane = tid & 31;
    const int w    = tid >> 5;
    const int g    = lane >> 2;
    const int t    = lane & 3;
    const int mrows  = (w & 1) * 16;     // warp m-rows within BM=32
    const int ngroup = w >> 1;           // warp n-group (32 batches each)

    // ---- block -> (mt, kc) over active upper-triangular chunks ----
    int mt = 0, rem = blockIdx.x;
    while (rem >= NKC - (mt >> 1)) { rem -= NKC - (mt >> 1); mt++; }
    const int kc = (mt >> 1) + rem;
    const int i0 = mt * BM;
    const int k0 = kc * BK;

    // ---- stage W tiles: 32 rows x 64 bf16 = 8 uint4/row ----
    {
        int idx = tid;                          // 256 threads, 256 uint4 pairs
        int r = idx >> 3, c = idx & 7;
        *(uint4*)(Whi_s + r * SW + c * 8) =
            *(const uint4*)(g_Whi + (i0 + r) * NN + k0 + c * 8);
        *(uint4*)(Wlo_s + r * SW + c * 8) =
            *(const uint4*)(g_Wlo + (i0 + r) * NN + k0 + c * 8);
    }
    // ---- stage V tiles: 128 rows x 64 bf16 ----
    #pragma unroll
    for (int idx = tid; idx < 128 * 8; idx += 256) {
        int r = idx >> 3, c = idx & 7;
        *(uint4*)(Vhi_s + r * SW + c * 8) =
            *(const uint4*)(g_Vhi + r * NN + k0 + c * 8);
        *(uint4*)(Vlo_s + r * SW + c * 8) =
            *(const uint4*)(g_Vlo + r * NN + k0 + c * 8);
    }
    // ---- stage fp32 v for epilogue: ViT[r][b] = vec[b, i0+r] ----
    #pragma unroll
    for (int idx = tid; idx < 128 * 8; idx += 256) {
        int b = idx >> 3, rq = idx & 7;
        float4 v4 = *(const float4*)(vec + b * NN + i0 + rq * 4);
        ViT[(rq * 4 + 0) * 129 + b] = v4.x;
        ViT[(rq * 4 + 1) * 129 + b] = v4.y;
        ViT[(rq * 4 + 2) * 129 + b] = v4.z;
        ViT[(rq * 4 + 3) * 129 + b] = v4.w;
    }
    if (tid < BM) Ls[tid] = g_L[i0 + tid];
    __syncthreads();

    // ---- fragment addresses (match R7-verified per-lane layout) ----
    const int aRow = mrows + (lane & 15);
    const int aCol = (lane >> 4) << 3;
    const unsigned addrAhi = sbase + OFF_WHI + (unsigned)(aRow * SW + aCol) * 2u;
    const unsigned addrAlo = sbase + OFF_WLO + (unsigned)(aRow * SW + aCol) * 2u;
    const int bRowBase = ngroup * 32 + (lane & 7) + ((lane >> 4) << 3);
    const int bCol = ((lane >> 3) & 1) << 3;
    const unsigned addrBhi = sbase + OFF_VHI + (unsigned)(bRowBase * SW + bCol) * 2u;
    const unsigned addrBlo = sbase + OFF_VLO + (unsigned)(bRowBase * SW + bCol) * 2u;

    float d[4][4];
    #pragma unroll
    for (int nt = 0; nt < 4; nt++)
        #pragma unroll
        for (int k = 0; k < 4; k++) d[nt][k] = 0.0f;

    #pragma unroll
    for (int s = 0; s < 4; s++) {
        const unsigned koB = (unsigned)(s * 16) * 2u;
        unsigned ah[4], al[4];
        ldsm4(ah, addrAhi + koB);
        ldsm4(al, addrAlo + koB);
        #pragma unroll
        for (int p = 0; p < 4; p += 2) {
            const unsigned po = (unsigned)(p * 8 * SW) * 2u;
            unsigned bh[4], bl[4];
            ldsm4(bh, addrBhi + po + koB);
            ldsm4(bl, addrBlo + po + koB);
            mma16816(d[p],   ah, bh[0], bh[1]);   // Whi*vhi
            mma16816(d[p],   ah, bl[0], bl[1]);   // Whi*vlo
            mma16816(d[p],   al, bh[0], bh[1]);   // Wlo*vhi
            mma16816(d[p+1], ah, bh[2], bh[3]);
            mma16816(d[p+1], ah, bl[2], bl[3]);
            mma16816(d[p+1], al, bh[2], bh[3]);
        }
    }

    // ---- epilogue: q_partial[b] = sum_i v[b,i] * T[i,b] ----
    {
        const int r0 = mrows + g;
        #pragma unroll
        for (int nt = 0; nt < 4; nt++) {
            const int b0 = ngroup * 32 + nt * 8 + 2 * t;
            float sA = d[nt][0] * ViT[r0 * 129 + b0]
                     + d[nt][2] * ViT[(r0 + 8) * 129 + b0];
            float sB = d[nt][1] * ViT[r0 * 129 + b0 + 1]
                     + d[nt][3] * ViT[(r0 + 8) * 129 + b0 + 1];
            #pragma unroll
            for (int o = 4; o <= 16; o <<= 1) {
                sA += __shfl_xor_sync(0xffffffffu, sA, o);
                sB += __shfl_xor_sync(0xffffffffu, sB, o);
            }
            if (lane < 4) {                      // g == 0 lanes hold totals
                qsm[w * 32 + nt * 8 + 2 * t]     = sA;
                qsm[w * 32 + nt * 8 + 2 * t + 1] = sB;
            }
        }
    }
    __syncthreads();

    if (tid < BB) {
        const int b = tid, ng = b >> 5, bl = b & 31;
        float qp = qsm[(ng * 2) * 32 + bl] + qsm[(ng * 2 + 1) * 32 + bl];
        if (kc == (mt >> 1)) {                   // first active chunk: fold linear
            #pragma unroll 8
            for (int r = 0; r < BM; r++)
                qp += Ls[r] * ViT[r * 129 + b];
        }
        g_qpart[b][blockIdx.x] = qp;
    }

    // ---- ticket-based fused final reduce ----
    __threadfence();
    __syncthreads();
    if (tid == 0) *s_rank = atomicAdd(&g_done, 1u);
    __syncthreads();
    if (*s_rank == NBLK - 1) {
        __threadfence();
        if (tid < BB) {
            float s = 0.0f;
            const float4* p = (const float4*)(&g_qpart[tid][0]);
            #pragma unroll 4
            for (int k = 0; k < NBLK / 4; k++) {
                float4 v4 = p[k];
                s += v4.x + v4.y + v4.z + v4.w;
            }
            float C = 0.0f;
            #pragma unroll
            for (int k = 0; k < 32; k++) C += g_cpart[k];
            out[tid] = C + 2.0f * s;
        }
        if (tid == 0) g_done = 0;                // reset for next replay
    }
}

extern "C" void kernel_launch(void* const* d_in, const int* in_sizes, int n_in,
                              void* d_out, int out_size)
{
    const float* vec = (const float*)d_in[0];   // vector        [128, 1024]
    const float* W   = (const float*)d_in[1];   // interactions  [1024, 1024]
    float* out = (float*)d_out;                 // [128]

    cudaFuncSetAttribute(potts_gemm,
                         cudaFuncAttributeMaxDynamicSharedMemorySize, SMEM_BYTES);

    rowprep<<<128, 256>>>(W);
    csprep<<<32, 256>>>(W);
    vprep<<<BB, 256>>>(vec);
    potts_gemm<<<NBLK, 256, SMEM_BYTES>>>(vec, out);
}

// round 9
// speedup vs baseline: 1.2224x; 1.0851x over previous
#include <cuda_runtime.h>
#include <cuda_bf16.h>

#define NN   1024
#define BB   128
#define BM   32
#define BK   64
#define NKC  16              // k-chunks
#define NBLK 272             // active (mt,kc): kc >= mt/2
#define SW   72              // smem bf16 row stride (16B aligned, conflict-free)

// ---- device scratch (static; no allocation) ----
__device__ __nv_bfloat16 g_Whi[NN * NN];
__device__ __nv_bfloat16 g_Wlo[NN * NN];
__device__ __nv_bfloat16 g_Vhi[BB * NN];
__device__ __nv_bfloat16 g_Vlo[BB * NN];
__device__ float g_rs[NN];
__device__ float g_csp[4][NN];     // col-sum partials (4 i-quarters)
__device__ float g_cpart[128];     // partials of C = sum of masked W
__device__ float g_qpart[BB][NBLK];
__device__ unsigned int g_done = 0;

// ============ prep 1: mask + hi/lo split of W (+rs) and v, warp-per-row ======
__global__ __launch_bounds__(128)
void prep_split(const float* __restrict__ W, const float* __restrict__ vec)
{
    const int w    = threadIdx.x >> 5;
    const int lane = threadIdx.x & 31;
    const bool isW = (blockIdx.x < 256);
    const int row  = isW ? (blockIdx.x * 4 + w) : ((blockIdx.x - 256) * 4 + w);
    const float* src        = isW ? (W + row * NN) : (vec + row * NN);
    __nv_bfloat16* dhi      = isW ? (g_Whi + row * NN) : (g_Vhi + row * NN);
    __nv_bfloat16* dlo      = isW ? (g_Wlo + row * NN) : (g_Vlo + row * NN);

    float acc = 0.0f;
    #pragma unroll
    for (int gq = 0; gq < 4; gq++) {
        const int j = gq * 256 + lane * 8;
        float4 a = *(const float4*)(src + j);
        float4 b = *(const float4*)(src + j + 4);
        float v[8] = {a.x, a.y, a.z, a.w, b.x, b.y, b.z, b.w};
        unsigned hi4[4], lo4[4];
        #pragma unroll
        for (int e = 0; e < 8; e += 2) {
            float w0 = v[e], w1 = v[e + 1];
            if (isW) {
                if (j + e     < row) w0 = 0.0f;
                if (j + e + 1 < row) w1 = 0.0f;
                acc += w0 + w1;
            }
            __nv_bfloat16 h0 = __float2bfloat16(w0);
            __nv_bfloat16 h1 = __float2bfloat16(w1);
            __nv_bfloat16 l0 = __float2bfloat16(w0 - __bfloat162float(h0));
            __nv_bfloat16 l1 = __float2bfloat16(w1 - __bfloat162float(h1));
            hi4[e >> 1] = ((unsigned)*(unsigned short*)&h1 << 16) | *(unsigned short*)&h0;
            lo4[e >> 1] = ((unsigned)*(unsigned short*)&l1 << 16) | *(unsigned short*)&l0;
        }
        *(uint4*)(dhi + j) = make_uint4(hi4[0], hi4[1], hi4[2], hi4[3]);
        *(uint4*)(dlo + j) = make_uint4(lo4[0], lo4[1], lo4[2], lo4[3]);
    }
    if (isW) {
        #pragma unroll
        for (int o = 16; o > 0; o >>= 1) acc += __shfl_xor_sync(0xffffffffu, acc, o);
        if (lane == 0) g_rs[row] = acc;
    }
}

// ============ prep 2: masked col-sum partials + C partials ===================
__global__ __launch_bounds__(256)
void prep_cs(const float* __restrict__ W)
{
    __shared__ float colp[8][33];
    const int lane = threadIdx.x & 31;
    const int w    = threadIdx.x >> 5;
    const int jg   = blockIdx.x & 31;
    const int iq   = blockIdx.x >> 5;
    const int j    = jg * 32 + lane;
    const int ib   = iq * 256 + w * 32;

    float acc = 0.0f;
    #pragma unroll 8
    for (int ii = 0; ii < 32; ii++) {
        int i = ib + ii;
        float v = W[i * NN + j];
        acc += (j >= i) ? v : 0.0f;
    }
    colp[w][lane] = acc;
    __syncthreads();
    if (w == 0) {
        float cs = 0.0f;
        #pragma unroll
        for (int k = 0; k < 8; k++) cs += colp[k][lane];
        g_csp[iq][j] = cs;
        float t = cs;
        #pragma unroll
        for (int o = 16; o > 0; o >>= 1) t += __shfl_xor_sync(0xffffffffu, t, o);
        if (lane == 0) g_cpart[blockIdx.x] = t;
    }
}

// ======================= main GEMM ===========================================
static __device__ __forceinline__
void mma16816(float* d, const unsigned* a, unsigned b0, unsigned b1)
{
    asm volatile(
        "mma.sync.aligned.m16n8k16.row.col.f32.bf16.bf16.f32 "
        "{%0,%1,%2,%3}, {%4,%5,%6,%7}, {%8,%9}, {%0,%1,%2,%3};\n"
        : "+f"(d[0]), "+f"(d[1]), "+f"(d[2]), "+f"(d[3])
        : "r"(a[0]), "r"(a[1]), "r"(a[2]), "r"(a[3]), "r"(b0), "r"(b1));
}
static __device__ __forceinline__
void ldsm4(unsigned* r, unsigned addr)
{
    asm volatile("ldmatrix.sync.aligned.m8n8.x4.shared.b16 {%0,%1,%2,%3}, [%4];"
                 : "=r"(r[0]), "=r"(r[1]), "=r"(r[2]), "=r"(r[3]) : "r"(addr));
}
static __device__ __forceinline__
void cpa16(unsigned dst, const void* src)
{
    asm volatile("cp.async.cg.shared.global [%0], [%1], 16;\n"
                 :: "r"(dst), "l"(src));
}

// smem layout (bytes)
#define OFF_WHI   0u
#define OFF_WLO   4608u
#define OFF_VHI   9216u
#define OFF_VLO   27648u
#define OFF_VIT   46080u     // float [32][129]
#define OFF_LS    62592u     // float [32]
#define OFF_QSM   62720u     // float [8][32]
#define OFF_RANK  63744u
#define SMEM_BYTES 63760u

__global__ __launch_bounds__(256, 3)
void potts_gemm(const float* __restrict__ vec, float* __restrict__ out)
{
    extern __shared__ char smem[];
    float* ViT = (float*)(smem + OFF_VIT);            // [32][129]
    float* Ls  = (float*)(smem + OFF_LS);
    float* qsm = (float*)(smem + OFF_QSM);            // [8][32]
    unsigned* s_rank = (unsigned*)(smem + OFF_RANK);
    const unsigned sbase = (unsigned)__cvta_generic_to_shared(smem);

    const int tid  = threadIdx.x;
    const int lane = tid & 31;
    const int w    = tid >> 5;
    const int g    = lane >> 2;
    const int t    = lane & 3;
    const int mrows  = (w & 1) * 16;     // warp m-rows within BM=32
    const int ngroup = w >> 1;           // warp n-group (32 batches each)

    // ---- block -> (mt, kc) over active upper-triangular chunks ----
    int mt = 0, rem = blockIdx.x;
    while (rem >= NKC - (mt >> 1)) { rem -= NKC - (mt >> 1); mt++; }
    const int kc = (mt >> 1) + rem;
    const int i0 = mt * BM;
    const int k0 = kc * BK;

    // ---- async-stage W tiles: 32 rows x 64 bf16 = 8 uint4/row ----
    {
        int r = tid >> 3, c = tid & 7;
        unsigned off = (unsigned)(r * SW + c * 8) * 2u;
        cpa16(sbase + OFF_WHI + off, g_Whi + (i0 + r) * NN + k0 + c * 8);
        cpa16(sbase + OFF_WLO + off, g_Wlo + (i0 + r) * NN + k0 + c * 8);
    }
    // ---- async-stage V tiles: 128 rows x 64 bf16 ----
    #pragma unroll
    for (int idx = tid; idx < 128 * 8; idx += 256) {
        int r = idx >> 3, c = idx & 7;
        unsigned off = (unsigned)(r * SW + c * 8) * 2u;
        cpa16(sbase + OFF_VHI + off, g_Vhi + r * NN + k0 + c * 8);
        cpa16(sbase + OFF_VLO + off, g_Vlo + r * NN + k0 + c * 8);
    }
    asm volatile("cp.async.commit_group;\n" ::: "memory");

    // ---- stage fp32 v for epilogue: ViT[r][b] = vec[b, i0+r] (manual) ----
    #pragma unroll
    for (int idx = tid; idx < 128 * 8; idx += 256) {
        int b = idx >> 3, rq = idx & 7;
        float4 v4 = *(const float4*)(vec + b * NN + i0 + rq * 4);
        ViT[(rq * 4 + 0) * 129 + b] = v4.x;
        ViT[(rq * 4 + 1) * 129 + b] = v4.y;
        ViT[(rq * 4 + 2) * 129 + b] = v4.z;
        ViT[(rq * 4 + 3) * 129 + b] = v4.w;
    }
    if (tid < BM) {
        int i = i0 + tid;
        Ls[tid] = -0.5f * (g_rs[i] + g_csp[0][i] + g_csp[1][i]
                                   + g_csp[2][i] + g_csp[3][i]);
    }
    asm volatile("cp.async.wait_group 0;\n" ::: "memory");
    __syncthreads();

    // ---- fragment addresses (verified per-lane layout) ----
    const int aRow = mrows + (lane & 15);
    const int aCol = (lane >> 4) << 3;
    const unsigned addrAhi = sbase + OFF_WHI + (unsigned)(aRow * SW + aCol) * 2u;
    const unsigned addrAlo = sbase + OFF_WLO + (unsigned)(aRow * SW + aCol) * 2u;
    const int bRowBase = ngroup * 32 + (lane & 7) + ((lane >> 4) << 3);
    const int bCol = ((lane >> 3) & 1) << 3;
    const unsigned addrBhi = sbase + OFF_VHI + (unsigned)(bRowBase * SW + bCol) * 2u;
    const unsigned addrBlo = sbase + OFF_VLO + (unsigned)(bRowBase * SW + bCol) * 2u;

    float d[4][4];
    #pragma unroll
    for (int nt = 0; nt < 4; nt++)
        #pragma unroll
        for (int k = 0; k < 4; k++) d[nt][k] = 0.0f;

    #pragma unroll
    for (int s = 0; s < 4; s++) {
        const unsigned koB = (unsigned)(s * 16) * 2u;
        unsigned ah[4], al[4];
        ldsm4(ah, addrAhi + koB);
        ldsm4(al, addrAlo + koB);
        #pragma unroll
        for (int p = 0; p < 4; p += 2) {
            const unsigned po = (unsigned)(p * 8 * SW) * 2u;
            unsigned bh[4], bl[4];
            ldsm4(bh, addrBhi + po + koB);
            ldsm4(bl, addrBlo + po + koB);
            mma16816(d[p],   ah, bh[0], bh[1]);   // Whi*vhi
            mma16816(d[p],   ah, bl[0], bl[1]);   // Whi*vlo
            mma16816(d[p],   al, bh[0], bh[1]);   // Wlo*vhi
            mma16816(d[p+1], ah, bh[2], bh[3]);
            mma16816(d[p+1], ah, bl[2], bl[3]);
            mma16816(d[p+1], al, bh[2], bh[3]);
        }
    }

    // ---- epilogue: q_partial[b] = sum_i v[b,i] * T[i,b] ----
    {
        const int r0 = mrows + g;
        #pragma unroll
        for (int nt = 0; nt < 4; nt++) {
            const int b0 = ngroup * 32 + nt * 8 + 2 * t;
            float sA = d[nt][0] * ViT[r0 * 129 + b0]
                     + d[nt][2] * ViT[(r0 + 8) * 129 + b0];
            float sB = d[nt][1] * ViT[r0 * 129 + b0 + 1]
                     + d[nt][3] * ViT[(r0 + 8) * 129 + b0 + 1];
            #pragma unroll
            for (int o = 4; o <= 16; o <<= 1) {
                sA += __shfl_xor_sync(0xffffffffu, sA, o);
                sB += __shfl_xor_sync(0xffffffffu, sB, o);
            }
            if (lane < 4) {
                qsm[w * 32 + nt * 8 + 2 * t]     = sA;
                qsm[w * 32 + nt * 8 + 2 * t + 1] = sB;
            }
        }
    }
    __syncthreads();

    if (tid < BB) {
        const int b = tid, ng = b >> 5, bl = b & 31;
        float qp = qsm[(ng * 2) * 32 + bl] + qsm[(ng * 2 + 1) * 32 + bl];
        if (kc == (mt >> 1)) {                   // first active chunk: fold linear
            #pragma unroll 8
            for (int r = 0; r < BM; r++)
                qp += Ls[r] * ViT[r * 129 + b];
        }
        g_qpart[b][blockIdx.x] = qp;
    }

    // ---- ticket-based fused final reduce ----
    __threadfence();
    __syncthreads();
    if (tid == 0) *s_rank = atomicAdd(&g_done, 1u);
    __syncthreads();
    if (*s_rank == NBLK - 1) {
        __threadfence();
        if (tid < BB) {
            float s = 0.0f;
            const float4* p = (const float4*)(&g_qpart[tid][0]);
            #pragma unroll 4
            for (int k = 0; k < NBLK / 4; k++) {
                float4 v4 = p[k];
                s += v4.x + v4.y + v4.z + v4.w;
            }
            float C = 0.0f;
            #pragma unroll 8
            for (int k = 0; k < 128; k++) C += g_cpart[k];
            out[tid] = C + 2.0f * s;
        }
        if (tid == 0) g_done = 0;                // reset for next replay
    }
}

extern "C" void kernel_launch(void* const* d_in, const int* in_sizes, int n_in,
                              void* d_out, int out_size)
{
    const float* vec = (const float*)d_in[0];   // vector        [128, 1024]
    const float* W   = (const float*)d_in[1];   // interactions  [1024, 1024]
    float* out = (float*)d_out;                 // [128]

    cudaFuncSetAttribute(potts_gemm,
                         cudaFuncAttributeMaxDynamicSharedMemorySize, SMEM_BYTES);

    prep_split<<<288, 128>>>(W, vec);
    prep_cs<<<128, 256>>>(W);
    potts_gemm<<<NBLK, 256, SMEM_BYTES>>>(vec, out);
}

// round 10
// speedup vs baseline: 1.6060x; 1.3139x over previous
#include <cuda_runtime.h>
#include <cuda_bf16.h>

#define NN   1024
#define BB   128
#define BM   32
#define BK   64
#define NKC  16              // k-chunks
#define NBLK 272             // active (mt,kc): kc >= mt>>1
#define SW   72              // smem bf16 row stride (16B-aligned rows: 144B)

// ---- device scratch (static; no allocation) ----
__device__ float g_qpart[BB][NBLK];
__device__ unsigned int g_done = 0;

static __device__ __forceinline__
void mma16816(float* d, const unsigned* a, unsigned b0, unsigned b1)
{
    asm volatile(
        "mma.sync.aligned.m16n8k16.row.col.f32.bf16.bf16.f32 "
        "{%0,%1,%2,%3}, {%4,%5,%6,%7}, {%8,%9}, {%0,%1,%2,%3};\n"
        : "+f"(d[0]), "+f"(d[1]), "+f"(d[2]), "+f"(d[3])
        : "r"(a[0]), "r"(a[1]), "r"(a[2]), "r"(a[3]), "r"(b0), "r"(b1));
}
static __device__ __forceinline__
void ldsm4(unsigned* r, unsigned addr)
{
    asm volatile("ldmatrix.sync.aligned.m8n8.x4.shared.b16 {%0,%1,%2,%3}, [%4];"
                 : "=r"(r[0]), "=r"(r[1]), "=r"(r[2]), "=r"(r[3]) : "r"(addr));
}

// split 8 fp32 -> packed bf16x2 hi / lo quads
static __device__ __forceinline__
void split8(const float* v, uint4& hi, uint4& lo)
{
    unsigned h[4], l[4];
    #pragma unroll
    for (int e = 0; e < 8; e += 2) {
        __nv_bfloat16 h0 = __float2bfloat16(v[e]);
        __nv_bfloat16 h1 = __float2bfloat16(v[e + 1]);
        __nv_bfloat16 l0 = __float2bfloat16(v[e]     - __bfloat162float(h0));
        __nv_bfloat16 l1 = __float2bfloat16(v[e + 1] - __bfloat162float(h1));
        h[e >> 1] = ((unsigned)*(unsigned short*)&h1 << 16) | *(unsigned short*)&h0;
        l[e >> 1] = ((unsigned)*(unsigned short*)&l1 << 16) | *(unsigned short*)&l0;
    }
    hi = make_uint4(h[0], h[1], h[2], h[3]);
    lo = make_uint4(l[0], l[1], l[2], l[3]);
}

// smem layout (bytes)
#define OFF_WHI   0u         // bf16 [32][SW]
#define OFF_WLO   4608u
#define OFF_VHI   9216u      // bf16 [128][SW]
#define OFF_VLO   27648u
#define OFF_VIT   46080u     // float [32][129]
#define OFF_RST   62592u     // float [32]  masked tile row sums
#define OFF_QSM   62720u     // float [8][32]
#define OFF_RANK  63744u
#define SMEM_BYTES 63760u

__global__ __launch_bounds__(256, 3)
void potts_gemm(const float* __restrict__ vec, const float* __restrict__ W,
                float* __restrict__ out)
{
    extern __shared__ char smem[];
    __nv_bfloat16* Whi_s = (__nv_bfloat16*)(smem + OFF_WHI);
    __nv_bfloat16* Wlo_s = (__nv_bfloat16*)(smem + OFF_WLO);
    __nv_bfloat16* Vhi_s = (__nv_bfloat16*)(smem + OFF_VHI);
    __nv_bfloat16* Vlo_s = (__nv_bfloat16*)(smem + OFF_VLO);
    float* ViT = (float*)(smem + OFF_VIT);
    float* rsT = (float*)(smem + OFF_RST);
    float* qsm = (float*)(smem + OFF_QSM);
    unsigned* s_rank = (unsigned*)(smem + OFF_RANK);
    const unsigned sbase = (unsigned)__cvta_generic_to_shared(smem);

    const int tid  = threadIdx.x;
    const int lane = tid & 31;
    const int w    = tid >> 5;
    const int g    = lane >> 2;
    const int t    = lane & 3;
    const int mrows  = (w & 1) * 16;     // warp m-rows within BM=32
    const int ngroup = w >> 1;           // warp n-group (32 batches)

    // ---- block -> (mt, kc) over active upper-triangular chunks ----
    int mt = 0, rem = blockIdx.x;
    while (rem >= NKC - (mt >> 1)) { rem -= NKC - (mt >> 1); mt++; }
    const int kc = (mt >> 1) + rem;
    const int i0 = mt * BM;
    const int k0 = kc * BK;

    // ---- stage W tile: fp32 load + triu mask + hi/lo split + row sums ----
    {
        const int r  = tid >> 3;          // 0..31
        const int cb = (tid & 7) * 8;     // 0..56
        const float* src = W + (i0 + r) * NN + k0 + cb;
        float4 a = *(const float4*)(src);
        float4 b4 = *(const float4*)(src + 4);
        float v[8] = {a.x, a.y, a.z, a.w, b4.x, b4.y, b4.z, b4.w};
        float rsum = 0.0f;
        #pragma unroll
        for (int e = 0; e < 8; e++) {
            if (k0 + cb + e < i0 + r) v[e] = 0.0f;   // keep j >= i
            rsum += v[e];
        }
        uint4 hi, lo;
        split8(v, hi, lo);
        *(uint4*)(Whi_s + r * SW + cb) = hi;
        *(uint4*)(Wlo_s + r * SW + cb) = lo;
        rsum += __shfl_down_sync(0xffffffffu, rsum, 4, 8);
        rsum += __shfl_down_sync(0xffffffffu, rsum, 2, 8);
        rsum += __shfl_down_sync(0xffffffffu, rsum, 1, 8);
        if ((tid & 7) == 0) rsT[r] = rsum;
    }
    // ---- stage V tile (batches x k): fp32 load + split ----
    #pragma unroll
    for (int idx = tid; idx < 128 * 8; idx += 256) {
        const int r  = idx >> 3;          // batch
        const int cb = (idx & 7) * 8;
        const float* src = vec + r * NN + k0 + cb;
        float4 a = *(const float4*)(src);
        float4 b4 = *(const float4*)(src + 4);
        float v[8] = {a.x, a.y, a.z, a.w, b4.x, b4.y, b4.z, b4.w};
        uint4 hi, lo;
        split8(v, hi, lo);
        *(uint4*)(Vhi_s + r * SW + cb) = hi;
        *(uint4*)(Vlo_s + r * SW + cb) = lo;
    }
    // ---- stage fp32 v (m-slice) transposed: ViT[r][b] = vec[b, i0+r] ----
    #pragma unroll
    for (int idx = tid; idx < 128 * 8; idx += 256) {
        const int b = idx >> 3, rq = idx & 7;
        float4 v4 = *(const float4*)(vec + b * NN + i0 + rq * 4);
        ViT[(rq * 4 + 0) * 129 + b] = v4.x;
        ViT[(rq * 4 + 1) * 129 + b] = v4.y;
        ViT[(rq * 4 + 2) * 129 + b] = v4.z;
        ViT[(rq * 4 + 3) * 129 + b] = v4.w;
    }
    __syncthreads();

    // ---- fragment addresses (validated per-lane layout) ----
    const int aRow = mrows + (lane & 15);
    const int aCol = (lane >> 4) << 3;
    const unsigned addrAhi = sbase + OFF_WHI + (unsigned)(aRow * SW + aCol) * 2u;
    const unsigned addrAlo = sbase + OFF_WLO + (unsigned)(aRow * SW + aCol) * 2u;
    const int bRowBase = ngroup * 32 + (lane & 7) + ((lane >> 4) << 3);
    const int bCol = ((lane >> 3) & 1) << 3;
    const unsigned addrBhi = sbase + OFF_VHI + (unsigned)(bRowBase * SW + bCol) * 2u;
    const unsigned addrBlo = sbase + OFF_VLO + (unsigned)(bRowBase * SW + bCol) * 2u;

    float d[4][4];
    #pragma unroll
    for (int nt = 0; nt < 4; nt++)
        #pragma unroll
        for (int k = 0; k < 4; k++) d[nt][k] = 0.0f;

    #pragma unroll
    for (int s = 0; s < 4; s++) {
        const unsigned koB = (unsigned)(s * 16) * 2u;
        unsigned ah[4], al[4];
        ldsm4(ah, addrAhi + koB);
        ldsm4(al, addrAlo + koB);
        #pragma unroll
        for (int p = 0; p < 4; p += 2) {
            const unsigned po = (unsigned)(p * 8 * SW) * 2u;
            unsigned bh[4], bl[4];
            ldsm4(bh, addrBhi + po + koB);
            ldsm4(bl, addrBlo + po + koB);
            mma16816(d[p],   ah, bh[0], bh[1]);   // Whi*vhi
            mma16816(d[p],   ah, bl[0], bl[1]);   // Whi*vlo
            mma16816(d[p],   al, bh[0], bh[1]);   // Wlo*vhi
            mma16816(d[p+1], ah, bh[2], bh[3]);
            mma16816(d[p+1], ah, bl[2], bl[3]);
            mma16816(d[p+1], al, bh[2], bh[3]);
        }
    }

    // ---- epilogue: sum_i T[i,b]*(2 v - 1) - rsT[i]*v  (col-sum term folded) ----
    {
        const int r0 = mrows + g;
        const float rA = rsT[r0], rB = rsT[r0 + 8];
        #pragma unroll
        for (int nt = 0; nt < 4; nt++) {
            const int b0 = ngroup * 32 + nt * 8 + 2 * t;
            const float v00 = ViT[r0 * 129 + b0];
            const float v10 = ViT[(r0 + 8) * 129 + b0];
            const float v01 = ViT[r0 * 129 + b0 + 1];
            const float v11 = ViT[(r0 + 8) * 129 + b0 + 1];
            float sA = d[nt][0] * (2.0f * v00 - 1.0f)
                     + d[nt][2] * (2.0f * v10 - 1.0f)
                     - rA * v00 - rB * v10;
            float sB = d[nt][1] * (2.0f * v01 - 1.0f)
                     + d[nt][3] * (2.0f * v11 - 1.0f)
                     - rA * v01 - rB * v11;
            #pragma unroll
            for (int o = 4; o <= 16; o <<= 1) {
                sA += __shfl_xor_sync(0xffffffffu, sA, o);
                sB += __shfl_xor_sync(0xffffffffu, sB, o);
            }
            if (lane < 4) {
                qsm[w * 32 + nt * 8 + 2 * t]     = sA;
                qsm[w * 32 + nt * 8 + 2 * t + 1] = sB;
            }
        }
    }
    __syncthreads();

    if (tid < BB) {
        const int ng = tid >> 5, bl = tid & 31;
        float Ct = 0.0f;                         // tile sum of masked W
        #pragma unroll 8
        for (int r = 0; r < BM; r++) Ct += rsT[r];
        g_qpart[tid][blockIdx.x] =
            qsm[(ng * 2) * 32 + bl] + qsm[(ng * 2 + 1) * 32 + bl] + Ct;
    }

    // ---- ticket-based fused final reduce ----
    __threadfence();
    __syncthreads();
    if (tid == 0) *s_rank = atomicAdd(&g_done, 1u);
    __syncthreads();
    if (*s_rank == NBLK - 1) {
        __threadfence();
        if (tid < BB) {
            float s = 0.0f;
            const float4* p = (const float4*)(&g_qpart[tid][0]);
            #pragma unroll 4
            for (int k = 0; k < NBLK / 4; k++) {
                float4 v4 = p[k];
                s += v4.x + v4.y + v4.z + v4.w;
            }
            out[tid] = s;
        }
        if (tid == 0) g_done = 0;                // reset for next replay
    }
}

extern "C" void kernel_launch(void* const* d_in, const int* in_sizes, int n_in,
                              void* d_out, int out_size)
{
    const float* vec = (const float*)d_in[0];   // vector        [128, 1024]
    const float* W   = (const float*)d_in[1];   // interactions  [1024, 1024]
    float* out = (float*)d_out;                 // [128]

    cudaFuncSetAttribute(potts_gemm,
                         cudaFuncAttributeMaxDynamicSharedMemorySize, SMEM_BYTES);
    potts_gemm<<<NBLK, 256, SMEM_BYTES>>>(vec, W, out);
}

// round 11
// speedup vs baseline: 1.6250x; 1.0118x over previous
#include <cuda_runtime.h>
#include <cuda_bf16.h>

#define NN   1024
#define BB   128
#define BM   32
#define BK   64
#define NKC  16              // k-chunks
#define NBLK 272             // active (mt,kc): kc >= mt>>1
#define SW   72              // smem bf16 row stride (rows 144B, 16B-aligned)

// ---- device scratch (static; no allocation) ----
__device__ __nv_bfloat16 g_Vhi[BB * NN];     // pre-split v (hi)
__device__ __nv_bfloat16 g_Vlo[BB * NN];     // pre-split v (lo)
__device__ float g_vecT[NN * BB];            // v transposed [k][b]
__device__ float g_qpart[BB][NBLK];
__device__ unsigned int g_done = 0;

static __device__ __forceinline__
void mma16816(float* d, const unsigned* a, unsigned b0, unsigned b1)
{
    asm volatile(
        "mma.sync.aligned.m16n8k16.row.col.f32.bf16.bf16.f32 "
        "{%0,%1,%2,%3}, {%4,%5,%6,%7}, {%8,%9}, {%0,%1,%2,%3};\n"
        : "+f"(d[0]), "+f"(d[1]), "+f"(d[2]), "+f"(d[3])
        : "r"(a[0]), "r"(a[1]), "r"(a[2]), "r"(a[3]), "r"(b0), "r"(b1));
}
static __device__ __forceinline__
void ldsm4(unsigned* r, unsigned addr)
{
    asm volatile("ldmatrix.sync.aligned.m8n8.x4.shared.b16 {%0,%1,%2,%3}, [%4];"
                 : "=r"(r[0]), "=r"(r[1]), "=r"(r[2]), "=r"(r[3]) : "r"(addr));
}
static __device__ __forceinline__
void cpa16(unsigned dst, const void* src)
{
    asm volatile("cp.async.cg.shared.global [%0], [%1], 16;\n" :: "r"(dst), "l"(src));
}

// split 8 fp32 -> packed bf16x2 hi / lo quads
static __device__ __forceinline__
void split8(const float* v, uint4& hi, uint4& lo)
{
    unsigned h[4], l[4];
    #pragma unroll
    for (int e = 0; e < 8; e += 2) {
        __nv_bfloat16 h0 = __float2bfloat16(v[e]);
        __nv_bfloat16 h1 = __float2bfloat16(v[e + 1]);
        __nv_bfloat16 l0 = __float2bfloat16(v[e]     - __bfloat162float(h0));
        __nv_bfloat16 l1 = __float2bfloat16(v[e + 1] - __bfloat162float(h1));
        h[e >> 1] = ((unsigned)*(unsigned short*)&h1 << 16) | *(unsigned short*)&h0;
        l[e >> 1] = ((unsigned)*(unsigned short*)&l1 << 16) | *(unsigned short*)&l0;
    }
    hi = make_uint4(h[0], h[1], h[2], h[3]);
    lo = make_uint4(l[0], l[1], l[2], l[3]);
}

// ================= prep: split v (bf16 hi/lo) + transpose (fp32) =============
__global__ __launch_bounds__(256)
void vprep(const float* __restrict__ vec)
{
    __shared__ float T[32][65];
    const int tid = threadIdx.x;
    const int bt = blockIdx.x >> 4;          // 0..3  (batch tile of 32)
    const int kt = blockIdx.x & 15;          // 0..15 (k tile of 64)
    const int b0 = bt * 32, k0 = kt * 64;

    {   // load 32b x 64k, split, store hi/lo + keep fp32 in smem
        const int r = tid >> 3, c = (tid & 7) * 8;
        const float* src = vec + (b0 + r) * NN + k0 + c;
        float4 a = *(const float4*)(src);
        float4 b4 = *(const float4*)(src + 4);
        float v[8] = {a.x, a.y, a.z, a.w, b4.x, b4.y, b4.z, b4.w};
        uint4 hi, lo;
        split8(v, hi, lo);
        *(uint4*)(g_Vhi + (b0 + r) * NN + k0 + c) = hi;
        *(uint4*)(g_Vlo + (b0 + r) * NN + k0 + c) = lo;
        #pragma unroll
        for (int e = 0; e < 8; e++) T[r][c + e] = v[e];
    }
    __syncthreads();
    {   // write transposed: g_vecT[k][b], 32B per thread
        const int k = tid >> 2, bq = (tid & 3) * 8;
        float o[8];
        #pragma unroll
        for (int e = 0; e < 8; e++) o[e] = T[bq + e][k];
        *(float4*)(g_vecT + (k0 + k) * BB + b0 + bq)     = make_float4(o[0], o[1], o[2], o[3]);
        *(float4*)(g_vecT + (k0 + k) * BB + b0 + bq + 4) = make_float4(o[4], o[5], o[6], o[7]);
    }
}

// smem layout (bytes)
#define OFF_WHI   0u         // bf16 [32][SW]
#define OFF_WLO   4608u
#define OFF_VHI   9216u      // bf16 [128][SW]
#define OFF_VLO   27648u
#define OFF_VIT   46080u     // float [32][132]
#define OFF_RST   62976u     // float [32]
#define OFF_QSM   63104u     // float [8][32]
#define OFF_RANK  64128u
#define SMEM_BYTES 64144u

__global__ __launch_bounds__(256, 3)
void potts_gemm(const float* __restrict__ vec, const float* __restrict__ W,
                float* __restrict__ out)
{
    extern __shared__ char smem[];
    __nv_bfloat16* Whi_s = (__nv_bfloat16*)(smem + OFF_WHI);
    __nv_bfloat16* Wlo_s = (__nv_bfloat16*)(smem + OFF_WLO);
    float* ViT = (float*)(smem + OFF_VIT);
    float* rsT = (float*)(smem + OFF_RST);
    float* qsm = (float*)(smem + OFF_QSM);
    unsigned* s_rank = (unsigned*)(smem + OFF_RANK);
    const unsigned sbase = (unsigned)__cvta_generic_to_shared(smem);

    const int tid  = threadIdx.x;
    const int lane = tid & 31;
    const int w    = tid >> 5;
    const int g    = lane >> 2;
    const int t    = lane & 3;
    const int mrows  = (w & 1) * 16;
    const int ngroup = w >> 1;

    // ---- block -> (mt, kc) over active upper-triangular chunks ----
    int mt = 0, rem = blockIdx.x;
    while (rem >= NKC - (mt >> 1)) { rem -= NKC - (mt >> 1); mt++; }
    const int kc = (mt >> 1) + rem;
    const int i0 = mt * BM;
    const int k0 = kc * BK;

    // ---- async-stage V hi/lo tiles (pre-split): 128 rows x 8 chunks each ----
    #pragma unroll
    for (int it = 0; it < 4; it++) {
        const int idx = tid + it * 256;           // 0..1023
        const int r = idx >> 3, c = (idx & 7) * 8;
        const unsigned off = (unsigned)(r * SW + c) * 2u;
        cpa16(sbase + OFF_VHI + off, g_Vhi + r * NN + k0 + c);
        cpa16(sbase + OFF_VLO + off, g_Vlo + r * NN + k0 + c);
    }
    // ---- async-stage ViT from pre-transposed vecT: 32 rows x 32 chunks ----
    #pragma unroll
    for (int it = 0; it < 4; it++) {
        const int idx = tid + it * 256;           // 0..1023
        const int r = idx >> 5, c4 = (idx & 31) * 4;
        cpa16(sbase + OFF_VIT + (unsigned)(r * 132 + c4) * 4u,
              g_vecT + (i0 + r) * BB + c4);
    }
    asm volatile("cp.async.commit_group;\n" ::: "memory");

    // ---- W tile: fp32 load + triu mask + hi/lo split + row sums (overlaps) ----
    {
        const int r  = tid >> 3;
        const int cb = (tid & 7) * 8;
        const float* src = W + (i0 + r) * NN + k0 + cb;
        float4 a = *(const float4*)(src);
        float4 b4 = *(const float4*)(src + 4);
        float v[8] = {a.x, a.y, a.z, a.w, b4.x, b4.y, b4.z, b4.w};
        float rsum = 0.0f;
        #pragma unroll
        for (int e = 0; e < 8; e++) {
            if (k0 + cb + e < i0 + r) v[e] = 0.0f;   // keep j >= i
            rsum += v[e];
        }
        uint4 hi, lo;
        split8(v, hi, lo);
        *(uint4*)(Whi_s + r * SW + cb) = hi;
        *(uint4*)(Wlo_s + r * SW + cb) = lo;
        rsum += __shfl_down_sync(0xffffffffu, rsum, 4, 8);
        rsum += __shfl_down_sync(0xffffffffu, rsum, 2, 8);
        rsum += __shfl_down_sync(0xffffffffu, rsum, 1, 8);
        if ((tid & 7) == 0) rsT[r] = rsum;
    }
    asm volatile("cp.async.wait_group 0;\n" ::: "memory");
    __syncthreads();

    // ---- fragment addresses (validated layout) ----
    const int aRow = mrows + (lane & 15);
    const int aCol = (lane >> 4) << 3;
    const unsigned addrAhi = sbase + OFF_WHI + (unsigned)(aRow * SW + aCol) * 2u;
    const unsigned addrAlo = sbase + OFF_WLO + (unsigned)(aRow * SW + aCol) * 2u;
    const int bRowBase = ngroup * 32 + (lane & 7) + ((lane >> 4) << 3);
    const int bCol = ((lane >> 3) & 1) << 3;
    const unsigned addrBhi = sbase + OFF_VHI + (unsigned)(bRowBase * SW + bCol) * 2u;
    const unsigned addrBlo = sbase + OFF_VLO + (unsigned)(bRowBase * SW + bCol) * 2u;

    float d[4][4];
    #pragma unroll
    for (int nt = 0; nt < 4; nt++)
        #pragma unroll
        for (int k = 0; k < 4; k++) d[nt][k] = 0.0f;

    #pragma unroll
    for (int s = 0; s < 4; s++) {
        const unsigned koB = (unsigned)(s * 16) * 2u;
        unsigned ah[4], al[4];
        ldsm4(ah, addrAhi + koB);
        ldsm4(al, addrAlo + koB);
        #pragma unroll
        for (int p = 0; p < 4; p += 2) {
            const unsigned po = (unsigned)(p * 8 * SW) * 2u;
            unsigned bh[4], bl[4];
            ldsm4(bh, addrBhi + po + koB);
            ldsm4(bl, addrBlo + po + koB);
            mma16816(d[p],   ah, bh[0], bh[1]);   // Whi*vhi
            mma16816(d[p],   ah, bl[0], bl[1]);   // Whi*vlo
            mma16816(d[p],   al, bh[0], bh[1]);   // Wlo*vhi
            mma16816(d[p+1], ah, bh[2], bh[3]);
            mma16816(d[p+1], ah, bl[2], bl[3]);
            mma16816(d[p+1], al, bh[2], bh[3]);
        }
    }

    // ---- epilogue: sum_i T[i,b]*(2v-1) - rsT[i]*v (col-sum folded into T) ----
    {
        const int r0 = mrows + g;
        const float rA = rsT[r0], rB = rsT[r0 + 8];
        #pragma unroll
        for (int nt = 0; nt < 4; nt++) {
            const int b0 = ngroup * 32 + nt * 8 + 2 * t;
            const float v00 = ViT[r0 * 132 + b0];
            const float v10 = ViT[(r0 + 8) * 132 + b0];
            const float v01 = ViT[r0 * 132 + b0 + 1];
            const float v11 = ViT[(r0 + 8) * 132 + b0 + 1];
            float sA = d[nt][0] * (2.0f * v00 - 1.0f)
                     + d[nt][2] * (2.0f * v10 - 1.0f)
                     - rA * v00 - rB * v10;
            float sB = d[nt][1] * (2.0f * v01 - 1.0f)
                     + d[nt][3] * (2.0f * v11 - 1.0f)
                     - rA * v01 - rB * v11;
            #pragma unroll
            for (int o = 4; o <= 16; o <<= 1) {
                sA += __shfl_xor_sync(0xffffffffu, sA, o);
                sB += __shfl_xor_sync(0xffffffffu, sB, o);
            }
            if (lane < 4) {
                qsm[w * 32 + nt * 8 + 2 * t]     = sA;
                qsm[w * 32 + nt * 8 + 2 * t + 1] = sB;
            }
        }
    }
    __syncthreads();

    if (tid < BB) {
        const int ng = tid >> 5, bl = tid & 31;
        float Ct = 0.0f;
        #pragma unroll 8
        for (int r = 0; r < BM; r++) Ct += rsT[r];
        g_qpart[tid][blockIdx.x] =
            qsm[(ng * 2) * 32 + bl] + qsm[(ng * 2 + 1) * 32 + bl] + Ct;
    }

    // ---- ticket-based fused final reduce ----
    __threadfence();
    __syncthreads();
    if (tid == 0) *s_rank = atomicAdd(&g_done, 1u);
    __syncthreads();
    if (*s_rank == NBLK - 1) {
        __threadfence();
        if (tid < BB) {
            float s = 0.0f;
            const float4* p = (const float4*)(&g_qpart[tid][0]);
            #pragma unroll 4
            for (int k = 0; k < NBLK / 4; k++) {
                float4 v4 = p[k];
                s += v4.x + v4.y + v4.z + v4.w;
            }
            out[tid] = s;
        }
        if (tid == 0) g_done = 0;
    }
}

extern "C" void kernel_launch(void* const* d_in, const int* in_sizes, int n_in,
                              void* d_out, int out_size)
{
    const float* vec = (const float*)d_in[0];   // vector        [128, 1024]
    const float* W   = (const float*)d_in[1];   // interactions  [1024, 1024]
    float* out = (float*)d_out;                 // [128]

    cudaFuncSetAttribute(potts_gemm,
                         cudaFuncAttributeMaxDynamicSharedMemorySize, SMEM_BYTES);
    vprep<<<64, 256>>>(vec);
    potts_gemm<<<NBLK, 256, SMEM_BYTES>>>(vec, W, out);
}